// round 4
// baseline (speedup 1.0000x reference)
#include <cuda_runtime.h>
#include <math.h>

#define T_   64
#define P_   144
#define C_   1024
#define MID_ 256
#define ROWS (T_ * P_)   // 9216

// ---------------- scratch (no allocations allowed) ----------------
__device__ float g_pooled[ROWS * C_];   // 37.7 MB
__device__ float g_q[ROWS * MID_];      //  9.4 MB
__device__ float g_r[ROWS * C_];        // 37.7 MB
__device__ float g_WkT[MID_ * C_];      //  1.0 MB

// ---------------- packed f32x2 helpers ----------------
__device__ __forceinline__ void ffma2(unsigned long long &acc,
                                      unsigned long long a,
                                      unsigned long long b) {
    asm("fma.rn.f32x2 %0, %1, %2, %0;" : "+l"(acc) : "l"(a), "l"(b));
}
__device__ __forceinline__ unsigned long long dup2(float a) {
    unsigned long long r;
    asm("mov.b64 %0, {%1, %1};" : "=l"(r) : "f"(a));
    return r;
}
__device__ __forceinline__ float2 unpk(unsigned long long v) {
    float2 f;
    asm("mov.b64 {%0, %1}, %2;" : "=f"(f.x), "=f"(f.y) : "l"(v));
    return f;
}

// ---------------- K1: 2x2 window average pool ----------------
// grid = 9216 blocks (one per (t, window)), 256 threads, float4/thread
__global__ void pool_kernel(const float* __restrict__ x) {
    int row = blockIdx.x;
    int t = row / P_, p = row % P_;
    int i = p / 12, j = p % 12;
    const float* base = x + ((size_t)t * 576 + (size_t)(2 * i) * 24 + 2 * j) * C_;
    int c = threadIdx.x * 4;
    float4 a = *(const float4*)(base + c);
    float4 b = *(const float4*)(base + C_ + c);
    float4 d = *(const float4*)(base + 24 * C_ + c);
    float4 e = *(const float4*)(base + 25 * C_ + c);
    float4 o;
    o.x = 0.25f * (a.x + b.x + d.x + e.x);
    o.y = 0.25f * (a.y + b.y + d.y + e.y);
    o.z = 0.25f * (a.z + b.z + d.z + e.z);
    o.w = 0.25f * (a.w + b.w + d.w + e.w);
    *(float4*)(g_pooled + (size_t)row * C_ + c) = o;
}

// ---------------- K2: transpose Wk [1024,256] -> WkT [256,1024] ----------------
__global__ void transpose_wk(const float* __restrict__ Wk) {
    __shared__ float s[32][33];
    int c0 = blockIdx.x * 32;   // over C_ (1024) -> 32 blocks
    int d0 = blockIdx.y * 32;   // over MID_ (256) -> 8 blocks
    int tx = threadIdx.x, ty = threadIdx.y;  // 32 x 8
#pragma unroll
    for (int u = 0; u < 32; u += 8)
        s[ty + u][tx] = Wk[(size_t)(c0 + ty + u) * MID_ + d0 + tx];
    __syncthreads();
#pragma unroll
    for (int u = 0; u < 32; u += 8)
        g_WkT[(size_t)(d0 + ty + u) * C_ + c0 + tx] = s[tx][ty + u];
}

// ---------------- K3/K4: 64x64 tiled fp32 GEMM, f32x2 FMAs ----------------
// C[M,N] = A[M,K] @ B[K,N] (+ bias[N] if bias != null)
// BM=BN=64, BK=16, 256 threads, 4x4 microtile per thread
__global__ void gemm64(const float* __restrict__ A, const float* __restrict__ B,
                       const float* __restrict__ bias, float* __restrict__ Cout,
                       int N, int K) {
    __shared__ float As[16][64];
    __shared__ float Bs[16][64];
    const int tid = threadIdx.x;
    const int tx = tid & 15, ty = tid >> 4;
    const int bm = blockIdx.x * 64, bn = blockIdx.y * 64;
    const int arow = tid >> 2, ak = (tid & 3) << 2;
    const int brow = tid >> 4, bcol = (tid & 15) << 2;

    unsigned long long acc[4][2];
#pragma unroll
    for (int i = 0; i < 4; i++) { acc[i][0] = 0ull; acc[i][1] = 0ull; }

    const float* Aptr = A + (size_t)(bm + arow) * K + ak;
    const float* Bptr = B + (size_t)brow * N + bn + bcol;

    for (int k0 = 0; k0 < K; k0 += 16) {
        float4 av = *(const float4*)(Aptr + k0);
        float4 bv = *(const float4*)(Bptr + (size_t)k0 * N);
        As[ak + 0][arow] = av.x;
        As[ak + 1][arow] = av.y;
        As[ak + 2][arow] = av.z;
        As[ak + 3][arow] = av.w;
        *(float4*)&Bs[brow][bcol] = bv;
        __syncthreads();
#pragma unroll
        for (int k = 0; k < 16; k++) {
            float4 a = *(const float4*)&As[k][ty << 2];
            ulonglong2 bb = *(const ulonglong2*)&Bs[k][tx << 2];
            unsigned long long a0 = dup2(a.x), a1 = dup2(a.y);
            unsigned long long a2 = dup2(a.z), a3 = dup2(a.w);
            ffma2(acc[0][0], a0, bb.x); ffma2(acc[0][1], a0, bb.y);
            ffma2(acc[1][0], a1, bb.x); ffma2(acc[1][1], a1, bb.y);
            ffma2(acc[2][0], a2, bb.x); ffma2(acc[2][1], a2, bb.y);
            ffma2(acc[3][0], a3, bb.x); ffma2(acc[3][1], a3, bb.y);
        }
        __syncthreads();
    }

    float4 bb = make_float4(0.f, 0.f, 0.f, 0.f);
    if (bias) bb = *(const float4*)&bias[bn + (tx << 2)];
#pragma unroll
    for (int i = 0; i < 4; i++) {
        float2 c0 = unpk(acc[i][0]);
        float2 c1 = unpk(acc[i][1]);
        float4 o;
        o.x = c0.x + bb.x;
        o.y = c0.y + bb.y;
        o.z = c1.x + bb.z;
        o.w = c1.y + bb.w;
        *(float4*)&Cout[(size_t)(bm + (ty << 2) + i) * N + bn + (tx << 2)] = o;
    }
}

// ---------------- K5: attention dots + softmax + weighted epilogue ----------------
// attn_w = ((r . x_w) + q.bk) / 16 ; out = sum_w (0.25 + softmax_w) * x_w
__global__ void attn_kernel(const float* __restrict__ x, const float* __restrict__ bk,
                            float* __restrict__ out) {
    int row = blockIdx.x;
    int t = row / P_, p = row % P_;
    int i = p / 12, j = p % 12;
    const float* xb = x + ((size_t)t * 576 + (size_t)(2 * i) * 24 + 2 * j) * C_;
    const float* rr = g_r + (size_t)row * C_;
    int tid = threadIdx.x;
    int c = tid * 4;

    float4 rv = *(const float4*)(rr + c);
    float4 x0 = *(const float4*)(xb + c);
    float4 x1 = *(const float4*)(xb + C_ + c);
    float4 x2 = *(const float4*)(xb + 24 * C_ + c);
    float4 x3 = *(const float4*)(xb + 25 * C_ + c);

    float s0 = rv.x * x0.x + rv.y * x0.y + rv.z * x0.z + rv.w * x0.w;
    float s1 = rv.x * x1.x + rv.y * x1.y + rv.z * x1.z + rv.w * x1.w;
    float s2 = rv.x * x2.x + rv.y * x2.y + rv.z * x2.z + rv.w * x2.w;
    float s3 = rv.x * x3.x + rv.y * x3.y + rv.z * x3.z + rv.w * x3.w;
    float qb = g_q[(size_t)row * MID_ + tid] * bk[tid];

#pragma unroll
    for (int off = 16; off > 0; off >>= 1) {
        s0 += __shfl_down_sync(0xffffffff, s0, off);
        s1 += __shfl_down_sync(0xffffffff, s1, off);
        s2 += __shfl_down_sync(0xffffffff, s2, off);
        s3 += __shfl_down_sync(0xffffffff, s3, off);
        qb += __shfl_down_sync(0xffffffff, qb, off);
    }

    __shared__ float red[8][5];
    __shared__ float coef[4];
    int lane = tid & 31, warp = tid >> 5;
    if (lane == 0) {
        red[warp][0] = s0; red[warp][1] = s1; red[warp][2] = s2;
        red[warp][3] = s3; red[warp][4] = qb;
    }
    __syncthreads();
    if (tid == 0) {
        float S[5] = {0.f, 0.f, 0.f, 0.f, 0.f};
#pragma unroll
        for (int w = 0; w < 8; w++)
#pragma unroll
            for (int k = 0; k < 5; k++) S[k] += red[w][k];
        const float scale = 0.0625f;  // 1/sqrt(256)
        float l0 = (S[0] + S[4]) * scale;
        float l1 = (S[1] + S[4]) * scale;
        float l2 = (S[2] + S[4]) * scale;
        float l3 = (S[3] + S[4]) * scale;
        float m = fmaxf(fmaxf(l0, l1), fmaxf(l2, l3));
        float e0 = expf(l0 - m), e1 = expf(l1 - m);
        float e2 = expf(l2 - m), e3 = expf(l3 - m);
        float inv = 1.0f / (e0 + e1 + e2 + e3);
        coef[0] = 0.25f + e0 * inv;
        coef[1] = 0.25f + e1 * inv;
        coef[2] = 0.25f + e2 * inv;
        coef[3] = 0.25f + e3 * inv;
    }
    __syncthreads();
    float c0 = coef[0], c1 = coef[1], c2 = coef[2], c3 = coef[3];
    float4 o;
    o.x = c0 * x0.x + c1 * x1.x + c2 * x2.x + c3 * x3.x;
    o.y = c0 * x0.y + c1 * x1.y + c2 * x2.y + c3 * x3.y;
    o.z = c0 * x0.z + c1 * x1.z + c2 * x2.z + c3 * x3.z;
    o.w = c0 * x0.w + c1 * x1.w + c2 * x2.w + c3 * x3.w;
    *(float4*)(out + (size_t)row * C_ + c) = o;
}

// ---------------- launch ----------------
extern "C" void kernel_launch(void* const* d_in, const int* in_sizes, int n_in,
                              void* d_out, int out_size) {
    const float* x  = (const float*)d_in[0];  // [64, 576, 1024]
    const float* Wq = (const float*)d_in[1];  // [1024, 256]
    const float* bq = (const float*)d_in[2];  // [256]
    const float* Wk = (const float*)d_in[3];  // [1024, 256]
    const float* bk = (const float*)d_in[4];  // [256]
    float* out = (float*)d_out;               // [64, 144, 1024]

    float* pooled; cudaGetSymbolAddress((void**)&pooled, g_pooled);
    float* q;      cudaGetSymbolAddress((void**)&q, g_q);
    float* r;      cudaGetSymbolAddress((void**)&r, g_r);
    float* wkt;    cudaGetSymbolAddress((void**)&wkt, g_WkT);

    pool_kernel<<<ROWS, 256>>>(x);
    transpose_wk<<<dim3(32, 8), dim3(32, 8)>>>(Wk);
    // q[9216,256] = pooled[9216,1024] @ Wq[1024,256] + bq
    gemm64<<<dim3(ROWS / 64, MID_ / 64), 256>>>(pooled, Wq, bq, q, MID_, C_);
    // r[9216,1024] = q[9216,256] @ WkT[256,1024]
    gemm64<<<dim3(ROWS / 64, C_ / 64), 256>>>(q, wkt, nullptr, r, C_, MID_);
    attn_kernel<<<ROWS, 256>>>(x, bk, out);
}

// round 6
// speedup vs baseline: 2.0775x; 2.0775x over previous
#include <cuda_runtime.h>
#include <math.h>
#include <cstdint>

#define T_   64
#define P_   144
#define C_   1024
#define MID_ 256
#define ROWS (T_ * P_)   // 9216

// ---------------- scratch (no allocations allowed) ----------------
__device__ float g_pooled[ROWS * C_];   // 37.7 MB
__device__ float g_q[ROWS * MID_];      //  9.4 MB
__device__ float g_r[ROWS * C_];        // 37.7 MB
__device__ float g_WT[MID_ * C_];       //  1.0 MB  (Wq^T)

__device__ __forceinline__ uint32_t f2tf32(float x) {
    uint32_t r;
    asm("cvt.rna.tf32.f32 %0, %1;" : "=r"(r) : "f"(x));
    return r;
}

__device__ __forceinline__ void mma_tf32(float& c0, float& c1, float& c2, float& c3,
                                         uint32_t a0, uint32_t a1, uint32_t a2, uint32_t a3,
                                         uint32_t b0, uint32_t b1) {
    asm volatile(
        "mma.sync.aligned.m16n8k8.row.col.f32.tf32.tf32.f32 "
        "{%0,%1,%2,%3}, {%4,%5,%6,%7}, {%8,%9}, {%0,%1,%2,%3};"
        : "+f"(c0), "+f"(c1), "+f"(c2), "+f"(c3)
        : "r"(a0), "r"(a1), "r"(a2), "r"(a3), "r"(b0), "r"(b1));
}

// ---------------- K1: 2x2 window average pool ----------------
__global__ void pool_kernel(const float* __restrict__ x) {
    int row = blockIdx.x;
    int t = row / P_, p = row % P_;
    int i = p / 12, j = p % 12;
    const float* base = x + ((size_t)t * 576 + (size_t)(2 * i) * 24 + 2 * j) * C_;
    int c = threadIdx.x * 4;
    float4 a = *(const float4*)(base + c);
    float4 b = *(const float4*)(base + C_ + c);
    float4 d = *(const float4*)(base + 24 * C_ + c);
    float4 e = *(const float4*)(base + 25 * C_ + c);
    float4 o;
    o.x = 0.25f * (a.x + b.x + d.x + e.x);
    o.y = 0.25f * (a.y + b.y + d.y + e.y);
    o.z = 0.25f * (a.z + b.z + d.z + e.z);
    o.w = 0.25f * (a.w + b.w + d.w + e.w);
    *(float4*)(g_pooled + (size_t)row * C_ + c) = o;
}

// ---------------- K2: transpose Wq [1024,256] -> WT [256,1024] ----------------
__global__ void transpose_w(const float* __restrict__ W) {
    __shared__ float s[32][33];
    int c0 = blockIdx.x * 32;
    int d0 = blockIdx.y * 32;
    int tx = threadIdx.x, ty = threadIdx.y;  // 32 x 8
#pragma unroll
    for (int u = 0; u < 32; u += 8)
        s[ty + u][tx] = W[(size_t)(c0 + ty + u) * MID_ + d0 + tx];
    __syncthreads();
#pragma unroll
    for (int u = 0; u < 32; u += 8)
        g_WT[(size_t)(d0 + ty + u) * C_ + c0 + tx] = s[tx][ty + u];
}

// ---------------- K3/K4: tf32 mma.sync GEMM ----------------
// D[M,N] = A[M,K](row-major) @ B[N,K]^T (+bias). BM=128, BN=64, BK=32.
// 128 threads = 4 warps in 2(m) x 2(n); warp tile 64x32 (4 mtiles x 4 ntiles).
// Smem XOR-swizzled: element (row,k) at row*32 + (k ^ ((row&7)<<2)).
__global__ void __launch_bounds__(128)
gemm_mma(const float* __restrict__ A, const float* __restrict__ B,
         const float* __restrict__ bias, float* __restrict__ Cout,
         int N, int K) {
    __shared__ uint32_t As[128 * 32];
    __shared__ uint32_t Bs[64 * 32];
    __shared__ float sBias[64];

    const int tid = threadIdx.x;
    const int lane = tid & 31, wid = tid >> 5;
    const int warp_m = wid >> 1, warp_n = wid & 1;
    const int bm = blockIdx.x * 128, bn = blockIdx.y * 64;

    if (tid < 64) sBias[tid] = bias ? bias[bn + tid] : 0.0f;

    const int g = lane >> 2;      // group id 0..7
    const int tk = lane & 3;      // thread-in-group
    const int sw = g << 2;        // XOR swizzle for this thread's fragment rows

    float acc[4][4][4];
#pragma unroll
    for (int i = 0; i < 4; i++)
#pragma unroll
        for (int j = 0; j < 4; j++)
#pragma unroll
            for (int f = 0; f < 4; f++) acc[i][j][f] = 0.0f;

    // global tile-load mapping: 8 float4 cols over K-chunk, 16-row strides
    const int lcol = tid & 7;          // float4 column (k/4)
    const int lrow = tid >> 3;         // 0..15
    const float* Ag = A + (size_t)(bm + lrow) * K + lcol * 4;
    const float* Bg = B + (size_t)(bn + lrow) * K + lcol * 4;

    for (int k0 = 0; k0 < K; k0 += 32) {
#pragma unroll
        for (int it = 0; it < 8; it++) {
            int row = lrow + it * 16;
            float4 v = *(const float4*)(Ag + (size_t)it * 16 * K + k0);
            int off = row * 32 + ((lcol * 4) ^ ((row & 7) << 2));
            uint4 u = make_uint4(f2tf32(v.x), f2tf32(v.y), f2tf32(v.z), f2tf32(v.w));
            *(uint4*)(As + off) = u;
        }
#pragma unroll
        for (int it = 0; it < 4; it++) {
            int row = lrow + it * 16;
            float4 v = *(const float4*)(Bg + (size_t)it * 16 * K + k0);
            int off = row * 32 + ((lcol * 4) ^ ((row & 7) << 2));
            uint4 u = make_uint4(f2tf32(v.x), f2tf32(v.y), f2tf32(v.z), f2tf32(v.w));
            *(uint4*)(Bs + off) = u;
        }
        __syncthreads();

#pragma unroll
        for (int ks = 0; ks < 4; ks++) {
            const int kx  = (ks * 8 + tk) ^ sw;
            const int kx4 = kx ^ 4;

            uint32_t af[4][4];
#pragma unroll
            for (int mt = 0; mt < 4; mt++) {
                int r = warp_m * 64 + mt * 16 + g;
                af[mt][0] = As[r * 32 + kx];
                af[mt][1] = As[(r + 8) * 32 + kx];
                af[mt][2] = As[r * 32 + kx4];
                af[mt][3] = As[(r + 8) * 32 + kx4];
            }
            uint32_t bf[4][2];
#pragma unroll
            for (int nt = 0; nt < 4; nt++) {
                int n = warp_n * 32 + nt * 8 + g;
                bf[nt][0] = Bs[n * 32 + kx];
                bf[nt][1] = Bs[n * 32 + kx4];
            }
#pragma unroll
            for (int mt = 0; mt < 4; mt++)
#pragma unroll
                for (int nt = 0; nt < 4; nt++)
                    mma_tf32(acc[mt][nt][0], acc[mt][nt][1],
                             acc[mt][nt][2], acc[mt][nt][3],
                             af[mt][0], af[mt][1], af[mt][2], af[mt][3],
                             bf[nt][0], bf[nt][1]);
        }
        __syncthreads();
    }

    // epilogue
#pragma unroll
    for (int mt = 0; mt < 4; mt++) {
#pragma unroll
        for (int nt = 0; nt < 4; nt++) {
            int r = bm + warp_m * 64 + mt * 16 + g;
            int cbase = warp_n * 32 + nt * 8 + tk * 2;
            float b0 = sBias[cbase], b1 = sBias[cbase + 1];
            int cg = bn + cbase;
            float2 o0 = make_float2(acc[mt][nt][0] + b0, acc[mt][nt][1] + b1);
            float2 o1 = make_float2(acc[mt][nt][2] + b0, acc[mt][nt][3] + b1);
            *(float2*)(Cout + (size_t)r * N + cg) = o0;
            *(float2*)(Cout + (size_t)(r + 8) * N + cg) = o1;
        }
    }
}

// ---------------- K5: attention dots + softmax + weighted epilogue ----------------
__global__ void attn_kernel(const float* __restrict__ x, const float* __restrict__ bk,
                            float* __restrict__ out) {
    int row = blockIdx.x;
    int t = row / P_, p = row % P_;
    int i = p / 12, j = p % 12;
    const float* xb = x + ((size_t)t * 576 + (size_t)(2 * i) * 24 + 2 * j) * C_;
    const float* rr = g_r + (size_t)row * C_;
    int tid = threadIdx.x;
    int c = tid * 4;

    float4 rv = *(const float4*)(rr + c);
    float4 x0 = *(const float4*)(xb + c);
    float4 x1 = *(const float4*)(xb + C_ + c);
    float4 x2 = *(const float4*)(xb + 24 * C_ + c);
    float4 x3 = *(const float4*)(xb + 25 * C_ + c);

    float s0 = rv.x * x0.x + rv.y * x0.y + rv.z * x0.z + rv.w * x0.w;
    float s1 = rv.x * x1.x + rv.y * x1.y + rv.z * x1.z + rv.w * x1.w;
    float s2 = rv.x * x2.x + rv.y * x2.y + rv.z * x2.z + rv.w * x2.w;
    float s3 = rv.x * x3.x + rv.y * x3.y + rv.z * x3.z + rv.w * x3.w;
    float qb = g_q[(size_t)row * MID_ + tid] * bk[tid];

#pragma unroll
    for (int off = 16; off > 0; off >>= 1) {
        s0 += __shfl_down_sync(0xffffffff, s0, off);
        s1 += __shfl_down_sync(0xffffffff, s1, off);
        s2 += __shfl_down_sync(0xffffffff, s2, off);
        s3 += __shfl_down_sync(0xffffffff, s3, off);
        qb += __shfl_down_sync(0xffffffff, qb, off);
    }

    __shared__ float red[8][5];
    __shared__ float coef[4];
    int lane = tid & 31, warp = tid >> 5;
    if (lane == 0) {
        red[warp][0] = s0; red[warp][1] = s1; red[warp][2] = s2;
        red[warp][3] = s3; red[warp][4] = qb;
    }
    __syncthreads();
    if (tid == 0) {
        float S[5] = {0.f, 0.f, 0.f, 0.f, 0.f};
#pragma unroll
        for (int w = 0; w < 8; w++)
#pragma unroll
            for (int k = 0; k < 5; k++) S[k] += red[w][k];
        const float scale = 0.0625f;  // 1/sqrt(256)
        float l0 = (S[0] + S[4]) * scale;
        float l1 = (S[1] + S[4]) * scale;
        float l2 = (S[2] + S[4]) * scale;
        float l3 = (S[3] + S[4]) * scale;
        float m = fmaxf(fmaxf(l0, l1), fmaxf(l2, l3));
        float e0 = expf(l0 - m), e1 = expf(l1 - m);
        float e2 = expf(l2 - m), e3 = expf(l3 - m);
        float inv = 1.0f / (e0 + e1 + e2 + e3);
        coef[0] = 0.25f + e0 * inv;
        coef[1] = 0.25f + e1 * inv;
        coef[2] = 0.25f + e2 * inv;
        coef[3] = 0.25f + e3 * inv;
    }
    __syncthreads();
    float c0 = coef[0], c1 = coef[1], c2 = coef[2], c3 = coef[3];
    float4 o;
    o.x = c0 * x0.x + c1 * x1.x + c2 * x2.x + c3 * x3.x;
    o.y = c0 * x0.y + c1 * x1.y + c2 * x2.y + c3 * x3.y;
    o.z = c0 * x0.z + c1 * x1.z + c2 * x2.z + c3 * x3.z;
    o.w = c0 * x0.w + c1 * x1.w + c2 * x2.w + c3 * x3.w;
    *(float4*)(out + (size_t)row * C_ + c) = o;
}

// ---------------- launch ----------------
extern "C" void kernel_launch(void* const* d_in, const int* in_sizes, int n_in,
                              void* d_out, int out_size) {
    const float* x  = (const float*)d_in[0];  // [64, 576, 1024]
    const float* Wq = (const float*)d_in[1];  // [1024, 256]
    const float* bq = (const float*)d_in[2];  // [256]
    const float* Wk = (const float*)d_in[3];  // [1024, 256]
    const float* bk = (const float*)d_in[4];  // [256]
    float* out = (float*)d_out;               // [64, 144, 1024]

    float* pooled; cudaGetSymbolAddress((void**)&pooled, g_pooled);
    float* q;      cudaGetSymbolAddress((void**)&q, g_q);
    float* r;      cudaGetSymbolAddress((void**)&r, g_r);
    float* wt;     cudaGetSymbolAddress((void**)&wt, g_WT);

    pool_kernel<<<ROWS, 256>>>(x);
    transpose_w<<<dim3(32, 8), dim3(32, 8)>>>(Wq);
    // q[9216,256] = pooled[9216,1024] @ Wq + bq   (B = Wq^T, K-major rows)
    gemm_mma<<<dim3(ROWS / 128, MID_ / 64), 128>>>(pooled, wt, bq, q, MID_, C_);
    // r[9216,1024] = q[9216,256] @ Wk^T           (B = Wk as-is, K-major rows)
    gemm_mma<<<dim3(ROWS / 128, C_ / 64), 128>>>(q, Wk, nullptr, r, C_, MID_);
    attn_kernel<<<ROWS, 256>>>(x, bk, out);
}